// round 8
// baseline (speedup 1.0000x reference)
#include <cuda_runtime.h>
#include <cuda_fp16.h>
#include <cuda_bf16.h>

// fp16 caches of L2-normalized rows. N = 100000, H = 128.
// g_en16: en (dst side). g_sd16: en*d (src side). 33.5 MB each, static.
#define MAX_N 131072
__device__ uint2 g_en16[MAX_N * 32];   // row*32 + lane -> 4 halves (8 B)
__device__ uint2 g_sd16[MAX_N * 32];

// Kernel A: one warp per row. Computes inv = 1/max(||row||, 1e-12), writes
// the normalized row as fp16 and the d-scaled normalized row as fp16.
__global__ void norm16_kernel(const float* __restrict__ emb,
                              const float* __restrict__ dvec, int N) {
    int row = blockIdx.x * (blockDim.x >> 5) + (threadIdx.x >> 5);
    if (row >= N) return;
    int lane = threadIdx.x & 31;
    const float4* r = reinterpret_cast<const float4*>(emb) + (size_t)row * 32;
    float4 v = r[lane];
    float4 dv = __ldg(reinterpret_cast<const float4*>(dvec) + lane);
    float ss = v.x * v.x + v.y * v.y + v.z * v.z + v.w * v.w;
    #pragma unroll
    for (int o = 16; o > 0; o >>= 1)
        ss += __shfl_xor_sync(0xffffffffu, ss, o);
    float inv = 1.0f / fmaxf(sqrtf(ss), 1e-12f);

    float nx = v.x * inv, ny = v.y * inv, nz = v.z * inv, nw = v.w * inv;

    __half2 h0 = __float22half2_rn(make_float2(nx, ny));
    __half2 h1 = __float22half2_rn(make_float2(nz, nw));
    uint2 pe;
    pe.x = *reinterpret_cast<unsigned int*>(&h0);
    pe.y = *reinterpret_cast<unsigned int*>(&h1);
    g_en16[(size_t)row * 32 + lane] = pe;

    __half2 s0 = __float22half2_rn(make_float2(nx * dv.x, ny * dv.y));
    __half2 s1 = __float22half2_rn(make_float2(nz * dv.z, nw * dv.w));
    uint2 ps;
    ps.x = *reinterpret_cast<unsigned int*>(&s0);
    ps.y = *reinterpret_cast<unsigned int*>(&s1);
    g_sd16[(size_t)row * 32 + lane] = ps;
}

// dot over 8 halves (one uint4 from each table), fp32 accumulate, no d.
__device__ __forceinline__ float dot8(uint4 a, uint4 b) {
    const __half2* pa = reinterpret_cast<const __half2*>(&a);
    const __half2* pb = reinterpret_cast<const __half2*>(&b);
    float ax = 0.0f, ay = 0.0f;
    #pragma unroll
    for (int k = 0; k < 4; k++) {
        float2 fa = __half22float2(pa[k]);
        float2 fb = __half22float2(pb[k]);
        ax += fa.x * fb.x;
        ay += fa.y * fb.y;
    }
    return ax + ay;
}

// Kernel B: persistent warps, 8 edges per warp per iteration. Two 4-edge
// sets; 8 lanes per edge; each lane issues 8 independent full-line LDG.128
// gathers. src rows come pre-multiplied by d, so the dot is a plain fma
// chain. Indices are int32 (JAX x64 disabled).
__global__ void __launch_bounds__(256) edge_kernel(
        const int* __restrict__ src,
        const int* __restrict__ dst,
        const float* __restrict__ scale,
        float* __restrict__ out,
        int E) {
    int lane = threadIdx.x & 31;
    int g    = lane >> 3;                // edge group: 0..3
    int l8   = lane & 7;                 // lane within group

    int warp_global = blockIdx.x * (blockDim.x >> 5) + (threadIdx.x >> 5);
    int nwarps      = gridDim.x * (blockDim.x >> 5);
    int stride      = nwarps * 8;

    float sc = __ldg(scale);
    const uint4* ens = reinterpret_cast<const uint4*>(g_sd16);   // src side
    const uint4* ent = reinterpret_cast<const uint4*>(g_en16);   // dst side

    int base = warp_global * 8;
    if (base >= E) return;

    // Prologue: indices for first iteration (clamped; stores are guarded).
    int eA = base + g, eB = base + 4 + g;
    int sA = __ldg(&src[min(eA, E - 1)]);
    int tA = __ldg(&dst[min(eA, E - 1)]);
    int sB = __ldg(&src[min(eB, E - 1)]);
    int tB = __ldg(&dst[min(eB, E - 1)]);

    for (; base < E; base += stride) {
        eA = base + g;
        eB = base + 4 + g;

        // Prefetch next iteration's indices off the critical path.
        int nb = base + stride;
        int sAn = 0, tAn = 0, sBn = 0, tBn = 0;
        if (nb < E) {
            int neA = min(nb + g, E - 1);
            int neB = min(nb + 4 + g, E - 1);
            sAn = __ldg(&src[neA]);
            tAn = __ldg(&dst[neA]);
            sBn = __ldg(&src[neB]);
            tBn = __ldg(&dst[neB]);
        }

        const uint4* rsA = ens + (size_t)sA * 16;
        const uint4* rtA = ent + (size_t)tA * 16;
        const uint4* rsB = ens + (size_t)sB * 16;
        const uint4* rtB = ent + (size_t)tB * 16;

        // 8 independent LDG.128; each row is 2 full 128 B lines.
        uint4 a0 = __ldg(&rsA[l8]);
        uint4 a1 = __ldg(&rsA[l8 + 8]);
        uint4 b0 = __ldg(&rtA[l8]);
        uint4 b1 = __ldg(&rtA[l8 + 8]);
        uint4 c0 = __ldg(&rsB[l8]);
        uint4 c1 = __ldg(&rsB[l8 + 8]);
        uint4 f0 = __ldg(&rtB[l8]);
        uint4 f1 = __ldg(&rtB[l8 + 8]);

        float pA = dot8(a0, b0) + dot8(a1, b1);
        float pB = dot8(c0, f0) + dot8(c1, f1);

        // Reduce each across the 8-lane group.
        #pragma unroll
        for (int o = 4; o > 0; o >>= 1) {
            pA += __shfl_xor_sync(0xffffffffu, pA, o);
            pB += __shfl_xor_sync(0xffffffffu, pB, o);
        }

        if (l8 == 0) {
            if (eA < E) out[eA] = pA * sc;   // lanes 0,8,16,24 -> coalesced
            if (eB < E) out[eB] = pB * sc;
        }

        sA = sAn; tA = tAn; sB = sBn; tB = tBn;
    }
}

extern "C" void kernel_launch(void* const* d_in, const int* in_sizes, int n_in,
                              void* d_out, int out_size) {
    const float* emb   = (const float*)d_in[0];
    const int*   src   = (const int*)d_in[1];
    const int*   dst   = (const int*)d_in[2];
    const float* dvec  = (const float*)d_in[3];
    const float* scale = (const float*)d_in[4];
    float* out = (float*)d_out;

    int N = in_sizes[0] / 128;   // H = 128
    int E = in_sizes[1];

    const int TPB = 256;
    int warps_per_block = TPB / 32;

    int norm_blocks = (N + warps_per_block - 1) / warps_per_block;
    norm16_kernel<<<norm_blocks, TPB>>>(emb, dvec, N);

    // Persistent-ish grid; each warp strides over 8-edge chunks.
    int edge_blocks = 148 * 8;
    int max_blocks = (E + warps_per_block * 8 - 1) / (warps_per_block * 8);
    if (edge_blocks > max_blocks) edge_blocks = max_blocks;
    edge_kernel<<<edge_blocks, TPB>>>(src, dst, scale, out, E);
}

// round 9
// speedup vs baseline: 1.1463x; 1.1463x over previous
#include <cuda_runtime.h>
#include <cuda_fp16.h>
#include <cuda_bf16.h>

// fp16 caches of L2-normalized rows. N = 100000, H = 128.
// g_en16: en (dst side). g_sd16: en*d (src side). 33.5 MB each, static.
#define MAX_N 131072
__device__ uint2 g_en16[MAX_N * 32];   // row*32 + lane -> 4 halves (8 B)
__device__ uint2 g_sd16[MAX_N * 32];

// Kernel A: one warp per row. Computes inv = 1/max(||row||, 1e-12), writes
// the normalized row as fp16 and the d-scaled normalized row as fp16.
// emb is read with streaming hint (__ldcs) so the 51 MB input does NOT evict
// the 67 MB of tables from L2 between graph replays.
__global__ void norm16_kernel(const float* __restrict__ emb,
                              const float* __restrict__ dvec, int N) {
    int row = blockIdx.x * (blockDim.x >> 5) + (threadIdx.x >> 5);
    if (row >= N) return;
    int lane = threadIdx.x & 31;
    const float4* r = reinterpret_cast<const float4*>(emb) + (size_t)row * 32;
    float4 v = __ldcs(&r[lane]);
    float4 dv = __ldg(reinterpret_cast<const float4*>(dvec) + lane);
    float ss = v.x * v.x + v.y * v.y + v.z * v.z + v.w * v.w;
    #pragma unroll
    for (int o = 16; o > 0; o >>= 1)
        ss += __shfl_xor_sync(0xffffffffu, ss, o);
    float inv = 1.0f / fmaxf(sqrtf(ss), 1e-12f);

    float nx = v.x * inv, ny = v.y * inv, nz = v.z * inv, nw = v.w * inv;

    __half2 h0 = __float22half2_rn(make_float2(nx, ny));
    __half2 h1 = __float22half2_rn(make_float2(nz, nw));
    uint2 pe;
    pe.x = *reinterpret_cast<unsigned int*>(&h0);
    pe.y = *reinterpret_cast<unsigned int*>(&h1);
    g_en16[(size_t)row * 32 + lane] = pe;

    __half2 s0 = __float22half2_rn(make_float2(nx * dv.x, ny * dv.y));
    __half2 s1 = __float22half2_rn(make_float2(nz * dv.z, nw * dv.w));
    uint2 ps;
    ps.x = *reinterpret_cast<unsigned int*>(&s0);
    ps.y = *reinterpret_cast<unsigned int*>(&s1);
    g_sd16[(size_t)row * 32 + lane] = ps;
}

// dot over 8 halves (one uint4 from each table), fp32 accumulate, no d.
__device__ __forceinline__ float dot8(uint4 a, uint4 b) {
    const __half2* pa = reinterpret_cast<const __half2*>(&a);
    const __half2* pb = reinterpret_cast<const __half2*>(&b);
    float ax = 0.0f, ay = 0.0f;
    #pragma unroll
    for (int k = 0; k < 4; k++) {
        float2 fa = __half22float2(pa[k]);
        float2 fb = __half22float2(pb[k]);
        ax += fa.x * fb.x;
        ay += fa.y * fb.y;
    }
    return ax + ay;
}

// Kernel B: persistent warps, 8 edges per warp per iteration. Two 4-edge
// sets; 8 lanes per edge; each lane issues 8 independent full-line LDG.128
// gathers. src rows come pre-multiplied by d, so the dot is a plain fma
// chain. Output written with streaming hint. Indices are int32.
__global__ void __launch_bounds__(256) edge_kernel(
        const int* __restrict__ src,
        const int* __restrict__ dst,
        const float* __restrict__ scale,
        float* __restrict__ out,
        int E) {
    int lane = threadIdx.x & 31;
    int g    = lane >> 3;                // edge group: 0..3
    int l8   = lane & 7;                 // lane within group

    int warp_global = blockIdx.x * (blockDim.x >> 5) + (threadIdx.x >> 5);
    int nwarps      = gridDim.x * (blockDim.x >> 5);
    int stride      = nwarps * 8;

    float sc = __ldg(scale);
    const uint4* ens = reinterpret_cast<const uint4*>(g_sd16);   // src side
    const uint4* ent = reinterpret_cast<const uint4*>(g_en16);   // dst side

    int base = warp_global * 8;
    if (base >= E) return;

    // Prologue: indices for first iteration (clamped; stores are guarded).
    int eA = base + g, eB = base + 4 + g;
    int sA = __ldg(&src[min(eA, E - 1)]);
    int tA = __ldg(&dst[min(eA, E - 1)]);
    int sB = __ldg(&src[min(eB, E - 1)]);
    int tB = __ldg(&dst[min(eB, E - 1)]);

    for (; base < E; base += stride) {
        eA = base + g;
        eB = base + 4 + g;

        // Prefetch next iteration's indices off the critical path.
        int nb = base + stride;
        int sAn = 0, tAn = 0, sBn = 0, tBn = 0;
        if (nb < E) {
            int neA = min(nb + g, E - 1);
            int neB = min(nb + 4 + g, E - 1);
            sAn = __ldg(&src[neA]);
            tAn = __ldg(&dst[neA]);
            sBn = __ldg(&src[neB]);
            tBn = __ldg(&dst[neB]);
        }

        const uint4* rsA = ens + (size_t)sA * 16;
        const uint4* rtA = ent + (size_t)tA * 16;
        const uint4* rsB = ens + (size_t)sB * 16;
        const uint4* rtB = ent + (size_t)tB * 16;

        // 8 independent LDG.128; each row is 2 full 128 B lines.
        uint4 a0 = __ldg(&rsA[l8]);
        uint4 a1 = __ldg(&rsA[l8 + 8]);
        uint4 b0 = __ldg(&rtA[l8]);
        uint4 b1 = __ldg(&rtA[l8 + 8]);
        uint4 c0 = __ldg(&rsB[l8]);
        uint4 c1 = __ldg(&rsB[l8 + 8]);
        uint4 f0 = __ldg(&rtB[l8]);
        uint4 f1 = __ldg(&rtB[l8 + 8]);

        float pA = dot8(a0, b0) + dot8(a1, b1);
        float pB = dot8(c0, f0) + dot8(c1, f1);

        // Reduce each across the 8-lane group.
        #pragma unroll
        for (int o = 4; o > 0; o >>= 1) {
            pA += __shfl_xor_sync(0xffffffffu, pA, o);
            pB += __shfl_xor_sync(0xffffffffu, pB, o);
        }

        if (l8 == 0) {
            if (eA < E) __stcs(&out[eA], pA * sc);   // streaming store
            if (eB < E) __stcs(&out[eB], pB * sc);
        }

        sA = sAn; tA = tAn; sB = sBn; tB = tBn;
    }
}

extern "C" void kernel_launch(void* const* d_in, const int* in_sizes, int n_in,
                              void* d_out, int out_size) {
    const float* emb   = (const float*)d_in[0];
    const int*   src   = (const int*)d_in[1];
    const int*   dst   = (const int*)d_in[2];
    const float* dvec  = (const float*)d_in[3];
    const float* scale = (const float*)d_in[4];
    float* out = (float*)d_out;

    int N = in_sizes[0] / 128;   // H = 128
    int E = in_sizes[1];

    const int TPB = 256;
    int warps_per_block = TPB / 32;

    int norm_blocks = (N + warps_per_block - 1) / warps_per_block;
    norm16_kernel<<<norm_blocks, TPB>>>(emb, dvec, N);

    // Persistent-ish grid; each warp strides over 8-edge chunks.
    int edge_blocks = 148 * 8;
    int max_blocks = (E + warps_per_block * 8 - 1) / (warps_per_block * 8);
    if (edge_blocks > max_blocks) edge_blocks = max_blocks;
    edge_kernel<<<edge_blocks, TPB>>>(src, dst, scale, out, E);
}

// round 10
// speedup vs baseline: 1.3268x; 1.1574x over previous
#include <cuda_runtime.h>
#include <cuda_fp16.h>
#include <cuda_bf16.h>

// fp16 cache of L2-normalized embedding rows. N = 100000, H = 128.
// Single 33.5 MB table -> stays L2-resident (two-table 67 MB variant thrashed).
#define MAX_N 131072
__device__ uint2 g_en16[MAX_N * 32];   // row*32 + lane -> 4 halves (8 B)

// Kernel A: one warp per row. inv = 1/max(||row||,1e-12); writes normalized
// row as fp16. emb read with streaming hint so it doesn't evict the table.
__global__ void norm16_kernel(const float* __restrict__ emb, int N) {
    int row = blockIdx.x * (blockDim.x >> 5) + (threadIdx.x >> 5);
    if (row >= N) return;
    int lane = threadIdx.x & 31;
    const float4* r = reinterpret_cast<const float4*>(emb) + (size_t)row * 32;
    float4 v = __ldcs(&r[lane]);
    float ss = v.x * v.x + v.y * v.y + v.z * v.z + v.w * v.w;
    #pragma unroll
    for (int o = 16; o > 0; o >>= 1)
        ss += __shfl_xor_sync(0xffffffffu, ss, o);
    float inv = 1.0f / fmaxf(sqrtf(ss), 1e-12f);

    __half2 h0 = __float22half2_rn(make_float2(v.x * inv, v.y * inv));
    __half2 h1 = __float22half2_rn(make_float2(v.z * inv, v.w * inv));
    uint2 pe;
    pe.x = *reinterpret_cast<unsigned int*>(&h0);
    pe.y = *reinterpret_cast<unsigned int*>(&h1);
    g_en16[(size_t)row * 32 + lane] = pe;
}

// Packed-half dot: (a .* d) . b over 8 halves, half2 accumulate.
__device__ __forceinline__ __half2 dot8h(uint4 a, uint4 b,
                                         const __half2* __restrict__ dh,
                                         __half2 acc) {
    const __half2* pa = reinterpret_cast<const __half2*>(&a);
    const __half2* pb = reinterpret_cast<const __half2*>(&b);
    #pragma unroll
    for (int k = 0; k < 4; k++)
        acc = __hfma2(__hmul2(pa[k], dh[k]), pb[k], acc);
    return acc;
}

// Kernel B: persistent warps, 8 edges per warp per iteration. Two 4-edge
// sets; 8 lanes per edge; each lane issues 8 independent full-line LDG.128
// gathers from the single table. d is held in 8 half2 registers per lane;
// the dot is HMUL2+HFMA2 packed math with fp32 finishing.
__global__ void __launch_bounds__(256) edge_kernel(
        const int* __restrict__ src,
        const int* __restrict__ dst,
        const float* __restrict__ dvec,
        const float* __restrict__ scale,
        float* __restrict__ out,
        int E) {
    int lane = threadIdx.x & 31;
    int g    = lane >> 3;                // edge group: 0..3
    int l8   = lane & 7;                 // lane within group

    int warp_global = blockIdx.x * (blockDim.x >> 5) + (threadIdx.x >> 5);
    int nwarps      = gridDim.x * (blockDim.x >> 5);
    int stride      = nwarps * 8;

    float sc = __ldg(scale);
    const uint4* en = reinterpret_cast<const uint4*>(g_en16);

    // Per-lane d slices as half2: elements [8*l8, 8*l8+8) and [64+8*l8, ...).
    __half2 d0[4], d1[4];
    {
        const float2* dp = reinterpret_cast<const float2*>(dvec);
        #pragma unroll
        for (int k = 0; k < 4; k++) {
            d0[k] = __float22half2_rn(__ldg(&dp[4 * l8 + k]));
            d1[k] = __float22half2_rn(__ldg(&dp[32 + 4 * l8 + k]));
        }
    }

    int base = warp_global * 8;
    if (base >= E) return;

    // Prologue indices (clamped; stores are guarded).
    int eA = base + g, eB = base + 4 + g;
    int sA = __ldg(&src[min(eA, E - 1)]);
    int tA = __ldg(&dst[min(eA, E - 1)]);
    int sB = __ldg(&src[min(eB, E - 1)]);
    int tB = __ldg(&dst[min(eB, E - 1)]);

    for (; base < E; base += stride) {
        eA = base + g;
        eB = base + 4 + g;

        // Prefetch next iteration's indices off the critical path.
        int nb = base + stride;
        int sAn = 0, tAn = 0, sBn = 0, tBn = 0;
        if (nb < E) {
            int neA = min(nb + g, E - 1);
            int neB = min(nb + 4 + g, E - 1);
            sAn = __ldg(&src[neA]);
            tAn = __ldg(&dst[neA]);
            sBn = __ldg(&src[neB]);
            tBn = __ldg(&dst[neB]);
        }

        const uint4* rsA = en + (size_t)sA * 16;
        const uint4* rtA = en + (size_t)tA * 16;
        const uint4* rsB = en + (size_t)sB * 16;
        const uint4* rtB = en + (size_t)tB * 16;

        // 8 independent LDG.128; each row is 2 full 128 B lines.
        uint4 a0 = __ldg(&rsA[l8]);
        uint4 a1 = __ldg(&rsA[l8 + 8]);
        uint4 b0 = __ldg(&rtA[l8]);
        uint4 b1 = __ldg(&rtA[l8 + 8]);
        uint4 c0 = __ldg(&rsB[l8]);
        uint4 c1 = __ldg(&rsB[l8 + 8]);
        uint4 f0 = __ldg(&rtB[l8]);
        uint4 f1 = __ldg(&rtB[l8 + 8]);

        __half2 z = __float2half2_rn(0.0f);
        __half2 aAcc = dot8h(a1, b1, d1, dot8h(a0, b0, d0, z));
        __half2 bAcc = dot8h(c1, f1, d1, dot8h(c0, f0, d0, z));

        float2 fA = __half22float2(aAcc);
        float2 fB = __half22float2(bAcc);
        float pA = fA.x + fA.y;
        float pB = fB.x + fB.y;

        // Reduce each across the 8-lane group (fp32).
        #pragma unroll
        for (int o = 4; o > 0; o >>= 1) {
            pA += __shfl_xor_sync(0xffffffffu, pA, o);
            pB += __shfl_xor_sync(0xffffffffu, pB, o);
        }

        if (l8 == 0) {
            if (eA < E) __stcs(&out[eA], pA * sc);
            if (eB < E) __stcs(&out[eB], pB * sc);
        }

        sA = sAn; tA = tAn; sB = sBn; tB = tBn;
    }
}

extern "C" void kernel_launch(void* const* d_in, const int* in_sizes, int n_in,
                              void* d_out, int out_size) {
    const float* emb   = (const float*)d_in[0];
    const int*   src   = (const int*)d_in[1];
    const int*   dst   = (const int*)d_in[2];
    const float* dvec  = (const float*)d_in[3];
    const float* scale = (const float*)d_in[4];
    float* out = (float*)d_out;

    int N = in_sizes[0] / 128;   // H = 128
    int E = in_sizes[1];

    const int TPB = 256;
    int warps_per_block = TPB / 32;

    int norm_blocks = (N + warps_per_block - 1) / warps_per_block;
    norm16_kernel<<<norm_blocks, TPB>>>(emb, N);

    // Persistent-ish grid; each warp strides over 8-edge chunks.
    int edge_blocks = 148 * 8;
    int max_blocks = (E + warps_per_block * 8 - 1) / (warps_per_block * 8);
    if (edge_blocks > max_blocks) edge_blocks = max_blocks;
    edge_kernel<<<edge_blocks, TPB>>>(src, dst, dvec, scale, out, E);
}

// round 11
// speedup vs baseline: 1.4134x; 1.0653x over previous
#include <cuda_runtime.h>
#include <cuda_fp16.h>
#include <cuda_bf16.h>

// fp16 cache of L2-normalized embedding rows. N = 100000, H = 128.
// Single 33.5 MB table -> stays L2-resident (two-table 67 MB variant thrashed).
#define MAX_N 131072
__device__ uint2 g_en16[MAX_N * 32];   // row*32 + lane -> 4 halves (8 B)

// Kernel A: one warp per row. inv = 1/max(||row||,1e-12); writes normalized
// row as fp16. emb read with streaming hint so it doesn't evict the table.
__global__ void norm16_kernel(const float* __restrict__ emb, int N) {
    int row = blockIdx.x * (blockDim.x >> 5) + (threadIdx.x >> 5);
    if (row >= N) return;
    int lane = threadIdx.x & 31;
    const float4* r = reinterpret_cast<const float4*>(emb) + (size_t)row * 32;
    float4 v = __ldcs(&r[lane]);
    float ss = v.x * v.x + v.y * v.y + v.z * v.z + v.w * v.w;
    #pragma unroll
    for (int o = 16; o > 0; o >>= 1)
        ss += __shfl_xor_sync(0xffffffffu, ss, o);
    float inv = 1.0f / fmaxf(sqrtf(ss), 1e-12f);

    __half2 h0 = __float22half2_rn(make_float2(v.x * inv, v.y * inv));
    __half2 h1 = __float22half2_rn(make_float2(v.z * inv, v.w * inv));
    uint2 pe;
    pe.x = *reinterpret_cast<unsigned int*>(&h0);
    pe.y = *reinterpret_cast<unsigned int*>(&h1);
    g_en16[(size_t)row * 32 + lane] = pe;
}

// Packed-half dot: (a .* d) . b over 8 halves, half2 accumulate.
__device__ __forceinline__ __half2 dot8h(uint4 a, uint4 b,
                                         const __half2* __restrict__ dh,
                                         __half2 acc) {
    const __half2* pa = reinterpret_cast<const __half2*>(&a);
    const __half2* pb = reinterpret_cast<const __half2*>(&b);
    #pragma unroll
    for (int k = 0; k < 4; k++)
        acc = __hfma2(__hmul2(pa[k], dh[k]), pb[k], acc);
    return acc;
}

// Kernel B: persistent warps, 8 edges per warp per iteration. Two 4-edge
// sets; 8 lanes per edge; 8 independent full-line LDG.128 gathers per lane.
// __launch_bounds__(256, 6): cap regs at ~42 so 6 blocks/SM fit (occ 75%).
__global__ void __launch_bounds__(256, 6) edge_kernel(
        const int* __restrict__ src,
        const int* __restrict__ dst,
        const float* __restrict__ dvec,
        const float* __restrict__ scale,
        float* __restrict__ out,
        int E) {
    int lane = threadIdx.x & 31;
    int g    = lane >> 3;                // edge group: 0..3
    int l8   = lane & 7;                 // lane within group

    int warp_global = blockIdx.x * (blockDim.x >> 5) + (threadIdx.x >> 5);
    int nwarps      = gridDim.x * (blockDim.x >> 5);
    int stride      = nwarps * 8;

    float sc = __ldg(scale);
    const uint4* en = reinterpret_cast<const uint4*>(g_en16);

    // Per-lane d slices as half2: elements [8*l8, 8*l8+8) and [64+8*l8, ...).
    __half2 d0[4], d1[4];
    {
        const float2* dp = reinterpret_cast<const float2*>(dvec);
        #pragma unroll
        for (int k = 0; k < 4; k++) {
            d0[k] = __float22half2_rn(__ldg(&dp[4 * l8 + k]));
            d1[k] = __float22half2_rn(__ldg(&dp[32 + 4 * l8 + k]));
        }
    }

    int base = warp_global * 8;
    if (base >= E) return;

    // Prologue indices (clamped; stores are guarded).
    int eA = base + g, eB = base + 4 + g;
    int sA = __ldg(&src[min(eA, E - 1)]);
    int tA = __ldg(&dst[min(eA, E - 1)]);
    int sB = __ldg(&src[min(eB, E - 1)]);
    int tB = __ldg(&dst[min(eB, E - 1)]);

    for (; base < E; base += stride) {
        eA = base + g;
        eB = base + 4 + g;

        // Prefetch next iteration's indices off the critical path.
        int nb = base + stride;
        int sAn = 0, tAn = 0, sBn = 0, tBn = 0;
        if (nb < E) {
            int neA = min(nb + g, E - 1);
            int neB = min(nb + 4 + g, E - 1);
            sAn = __ldg(&src[neA]);
            tAn = __ldg(&dst[neA]);
            sBn = __ldg(&src[neB]);
            tBn = __ldg(&dst[neB]);
        }

        const uint4* rsA = en + (size_t)sA * 16;
        const uint4* rtA = en + (size_t)tA * 16;
        const uint4* rsB = en + (size_t)sB * 16;
        const uint4* rtB = en + (size_t)tB * 16;

        // 8 independent LDG.128; each row is 2 full 128 B lines.
        uint4 a0 = __ldg(&rsA[l8]);
        uint4 a1 = __ldg(&rsA[l8 + 8]);
        uint4 b0 = __ldg(&rtA[l8]);
        uint4 b1 = __ldg(&rtA[l8 + 8]);
        uint4 c0 = __ldg(&rsB[l8]);
        uint4 c1 = __ldg(&rsB[l8 + 8]);
        uint4 f0 = __ldg(&rtB[l8]);
        uint4 f1 = __ldg(&rtB[l8 + 8]);

        __half2 z = __float2half2_rn(0.0f);
        __half2 aAcc = dot8h(a1, b1, d1, dot8h(a0, b0, d0, z));
        __half2 bAcc = dot8h(c1, f1, d1, dot8h(c0, f0, d0, z));

        float2 fA = __half22float2(aAcc);
        float2 fB = __half22float2(bAcc);
        float pA = fA.x + fA.y;
        float pB = fB.x + fB.y;

        // Reduce each across the 8-lane group (fp32).
        #pragma unroll
        for (int o = 4; o > 0; o >>= 1) {
            pA += __shfl_xor_sync(0xffffffffu, pA, o);
            pB += __shfl_xor_sync(0xffffffffu, pB, o);
        }

        if (l8 == 0) {
            if (eA < E) __stcs(&out[eA], pA * sc);
            if (eB < E) __stcs(&out[eB], pB * sc);
        }

        sA = sAn; tA = tAn; sB = sBn; tB = tBn;
    }
}

extern "C" void kernel_launch(void* const* d_in, const int* in_sizes, int n_in,
                              void* d_out, int out_size) {
    const float* emb   = (const float*)d_in[0];
    const int*   src   = (const int*)d_in[1];
    const int*   dst   = (const int*)d_in[2];
    const float* dvec  = (const float*)d_in[3];
    const float* scale = (const float*)d_in[4];
    float* out = (float*)d_out;

    int N = in_sizes[0] / 128;   // H = 128
    int E = in_sizes[1];

    const int TPB = 256;
    int warps_per_block = TPB / 32;

    int norm_blocks = (N + warps_per_block - 1) / warps_per_block;
    norm16_kernel<<<norm_blocks, TPB>>>(emb, N);

    // One exact wave: 6 blocks/SM * 148 SMs.
    int edge_blocks = 148 * 6;
    int max_blocks = (E + warps_per_block * 8 - 1) / (warps_per_block * 8);
    if (edge_blocks > max_blocks) edge_blocks = max_blocks;
    edge_kernel<<<edge_blocks, TPB>>>(src, dst, dvec, scale, out, E);
}